// round 15
// baseline (speedup 1.0000x reference)
#include <cuda_runtime.h>
#include <math.h>

#define N_LOC 4096
#define N_REP 128
#define M_NBR 48

// packed lower-triangle row offset (rows padded to multiples of 4)
__device__ __forceinline__ int aoff(int i) {
    int q = i >> 2;
    return 4 * (q + 1) * (2 * q + (i & 3));
}

__device__ __forceinline__ void tridec(int t, int& row, int& col) {
    int r = (int)((sqrtf(8.0f * (float)t + 1.0f) - 1.0f) * 0.5f);
    while ((r + 1) * (r + 2) / 2 <= t) ++r;
    while (r * (r + 1) / 2 > t) --r;
    row = r;
    col = t - r * (r + 1) / 2;
}

// ===================== Kernel 1: gram + Matern epilogue -> g + packed scratch ===
__global__ __launch_bounds__(512, 3)
void gram_kernel(const float* __restrict__ aug,
                 const float* __restrict__ theta,
                 const float* __restrict__ scales,
                 const float* __restrict__ nug_mean,
                 const int* __restrict__ batch_idx,
                 float* __restrict__ out)
{
    const int N = blockIdx.x;
    const int tid = threadIdx.x;
    float* g_out = out + (size_t)N * 16384;
    float* scr   = out + (size_t)N_LOC * 16384 + (size_t)N * 16384;  // packed scratch

    if (batch_idx[N] == 0) {
        for (int idx = tid; idx < 16384; idx += 512)
            g_out[idx] = ((idx >> 7) == (idx & 127)) ? 1.0f : 0.0f;
        // packed identity into scratch (chol(I) = I)
        for (int idx = tid; idx < 8448; idx += 512) scr[idx] = 0.0f;
        __syncthreads();
        if (tid < 128) scr[aoff(tid) + tid] = 1.0f;
        return;
    }

    __shared__ float xs[M_NBR * 128];
    __shared__ float diag[128];
    __shared__ float scalm[M_NBR];

    const float t2 = theta[2];
    const float t3 = theta[3];
    const float t4 = theta[4];
    const float t5 = theta[5];
    const float ls = expf(t5) * 1.7320508075688772f;
    const float inv_ls2 = 1.0f / (ls * ls);
    const float sig2 = expf(2.0f * (logf(scales[N]) * t4 + t3));
    const float inv_nug = 1.0f / nug_mean[N];

    if (tid < M_NBR)
        scalm[tid] = expf(-0.5f * (float)(tid + 1) * expf(t2));
    __syncthreads();

    {
        const float* base = aug + (size_t)N * (M_NBR + 1) + 1;
        for (int idx = tid; idx < N_REP * M_NBR; idx += 512) {
            int i = idx / M_NBR;
            int m = idx - i * M_NBR;
            float v = base[(size_t)i * ((size_t)N_LOC * (M_NBR + 1)) + m];
            if (v != v) v = 0.0f;
            xs[m * 128 + i] = v * scalm[m];
        }
    }
    __syncthreads();

    if (tid < N_REP) {
        float d = 0.0f;
        #pragma unroll
        for (int m = 0; m < M_NBR; ++m) {
            float v = xs[m * 128 + tid];
            d = fmaf(v, v, d);
        }
        diag[tid] = d;
    }
    __syncthreads();

    for (int t = tid; t < 528; t += 512) {
        int ti, tj;
        tridec(t, ti, tj);
        const int ib = ti * 4, jb = tj * 4;

        float acc[16];
        #pragma unroll
        for (int k = 0; k < 16; ++k) acc[k] = 0.0f;

        #pragma unroll 4
        for (int m = 0; m < M_NBR; ++m) {
            const float* row = xs + m * 128;
            float4 a = *reinterpret_cast<const float4*>(row + ib);
            float4 b = *reinterpret_cast<const float4*>(row + jb);
            float av[4] = {a.x, a.y, a.z, a.w};
            float bv[4] = {b.x, b.y, b.z, b.w};
            #pragma unroll
            for (int r = 0; r < 4; ++r)
                #pragma unroll
                for (int c = 0; c < 4; ++c)
                    acc[r * 4 + c] = fmaf(av[r], bv[c], acc[r * 4 + c]);
        }

        float di[4], dj[4];
        #pragma unroll
        for (int r = 0; r < 4; ++r) di[r] = diag[ib + r];
        #pragma unroll
        for (int c = 0; c < 4; ++c) dj[c] = diag[jb + c];

        #pragma unroll
        for (int r = 0; r < 4; ++r)
            #pragma unroll
            for (int c = 0; c < 4; ++c) {
                float G = acc[r * 4 + c];
                float sq = fmaxf((di[r] + dj[c] - 2.0f * G) * inv_ls2, 0.0f);
                float s3 = 1.7320508075688772f * sq * __frsqrt_rn(fmaxf(sq, 1e-30f));
                float mat = (1.0f + s3) * __expf(-s3);
                acc[r * 4 + c] = (G + sig2 * mat) * inv_nug
                               + ((ib + r == jb + c) ? 1.0f : 0.0f);
            }

        #pragma unroll
        for (int r = 0; r < 4; ++r)
            *reinterpret_cast<float4*>(g_out + (ib + r) * 128 + jb) =
                make_float4(acc[r * 4], acc[r * 4 + 1], acc[r * 4 + 2], acc[r * 4 + 3]);
        if (ti > tj) {
            #pragma unroll
            for (int c = 0; c < 4; ++c)
                *reinterpret_cast<float4*>(g_out + (jb + c) * 128 + ib) =
                    make_float4(acc[c], acc[4 + c], acc[8 + c], acc[12 + c]);
            // packed scratch: full tile
            #pragma unroll
            for (int r = 0; r < 4; ++r)
                *reinterpret_cast<float4*>(&scr[aoff(ib + r) + jb]) =
                    make_float4(acc[r * 4], acc[r * 4 + 1], acc[r * 4 + 2], acc[r * 4 + 3]);
        } else {
            // diagonal tile: lower part only
            #pragma unroll
            for (int r = 0; r < 4; ++r)
                #pragma unroll
                for (int c = 0; c < 4; ++c)
                    if (jb + c <= ib + r) scr[aoff(ib + r) + jb + c] = acc[r * 4 + c];
        }
    }
}

// ===================== Kernel 2: batched Cholesky ===============================

// Warp-cooperative rank-16 update of the 16x16 block (I,J) using panel cols
// [kp, kp+16). Panel blocks in registers; inner loop via shuffles.
__device__ __forceinline__ void warp_block_update(float* __restrict__ Apk,
                                                  int I, int J, int kp,
                                                  int lane, bool isdiag)
{
    const int lr = lane >> 3;
    const int lc = lane & 7;
    const int lrow = lane >> 1;            // local row loaded by this lane
    const int h8 = (lane & 1) << 3;        // column half (0 or 8)

    float areg[8], breg[8];
    {
        const float* p = &Apk[aoff((I << 4) + lrow) + kp + h8];
        float4 v0 = *reinterpret_cast<const float4*>(p);
        float4 v1 = *reinterpret_cast<const float4*>(p + 4);
        areg[0] = v0.x; areg[1] = v0.y; areg[2] = v0.z; areg[3] = v0.w;
        areg[4] = v1.x; areg[5] = v1.y; areg[6] = v1.z; areg[7] = v1.w;
    }
    if (isdiag) {
        #pragma unroll
        for (int q = 0; q < 8; ++q) breg[q] = areg[q];
    } else {
        const float* p = &Apk[aoff((J << 4) + lrow) + kp + h8];
        float4 v0 = *reinterpret_cast<const float4*>(p);
        float4 v1 = *reinterpret_cast<const float4*>(p + 4);
        breg[0] = v0.x; breg[1] = v0.y; breg[2] = v0.z; breg[3] = v0.w;
        breg[4] = v1.x; breg[5] = v1.y; breg[6] = v1.z; breg[7] = v1.w;
    }

    float acc[8];
    #pragma unroll
    for (int k = 0; k < 8; ++k) acc[k] = 0.0f;

    const int ra = lr << 2;   // first out row (local)
    const int ca = lc << 1;   // first out col (local)

    #pragma unroll
    for (int d = 0; d < 16; ++d) {
        const int dh = d >> 3;
        const int di = d & 7;
        float a0 = __shfl_sync(0xffffffffu, areg[di], ((ra + 0) << 1) | dh);
        float a1 = __shfl_sync(0xffffffffu, areg[di], ((ra + 1) << 1) | dh);
        float a2 = __shfl_sync(0xffffffffu, areg[di], ((ra + 2) << 1) | dh);
        float a3 = __shfl_sync(0xffffffffu, areg[di], ((ra + 3) << 1) | dh);
        float b0 = __shfl_sync(0xffffffffu, breg[di], ((ca + 0) << 1) | dh);
        float b1 = __shfl_sync(0xffffffffu, breg[di], ((ca + 1) << 1) | dh);
        acc[0] = fmaf(a0, b0, acc[0]); acc[1] = fmaf(a0, b1, acc[1]);
        acc[2] = fmaf(a1, b0, acc[2]); acc[3] = fmaf(a1, b1, acc[3]);
        acc[4] = fmaf(a2, b0, acc[4]); acc[5] = fmaf(a2, b1, acc[5]);
        acc[6] = fmaf(a3, b0, acc[6]); acc[7] = fmaf(a3, b1, acc[7]);
    }

    const int ob = (J << 4) + ca;
    #pragma unroll
    for (int r = 0; r < 4; ++r) {
        const int il = ra + r;
        float* p = &Apk[aoff((I << 4) + il) + ob];
        if (!isdiag) {
            float2 v = *reinterpret_cast<float2*>(p);
            v.x -= acc[r * 2 + 0];
            v.y -= acc[r * 2 + 1];
            *reinterpret_cast<float2*>(p) = v;
        } else {
            if (ca     <= il) p[0] -= acc[r * 2 + 0];
            if (ca + 1 <= il) p[1] -= acc[r * 2 + 1];
        }
    }
}

// warp0: factor 16x16 diag block at k0 (in Apk), produce invd + invL.
__device__ __forceinline__ void diag_factor(float* __restrict__ Apk,
                                            float* __restrict__ invd,
                                            float* __restrict__ invL,
                                            int k0, int lane)
{
    float rw[16];
    const int ro = (lane < 16) ? (aoff(k0 + lane) + k0) : 0;
    if (lane < 16) {
        #pragma unroll
        for (int j = 0; j < 16; ++j)
            rw[j] = (j <= lane) ? Apk[ro + j] : 0.0f;
    } else {
        #pragma unroll
        for (int j = 0; j < 16; ++j) rw[j] = 0.0f;
    }
    #pragma unroll
    for (int c = 0; c < 16; ++c) {
        float dcc = __shfl_sync(0xffffffffu, rw[c], c);
        float lcc = sqrtf(dcc);
        float inv = 1.0f / lcc;
        if (lane == c) { rw[c] = lcc; invd[c] = inv; }
        else if (lane > c && lane < 16) rw[c] *= inv;
        float vc = rw[c];
        #pragma unroll
        for (int j = c + 1; j < 16; ++j) {
            float vj = __shfl_sync(0xffffffffu, vc, j);
            if (lane >= j && lane < 16) rw[j] -= vc * vj;
        }
    }
    if (lane < 16) {
        #pragma unroll
        for (int j = 0; j < 16; ++j)
            if (j <= lane) Apk[ro + j] = rw[j];
    }
    __syncwarp();
    // inv(L11) column `lane`
    if (lane < 16) {
        float x[16];
        #pragma unroll
        for (int r = 0; r < 16; ++r) {
            float s = (r == lane) ? 1.0f : 0.0f;
            const int rr = aoff(k0 + r) + k0;
            #pragma unroll
            for (int d = 0; d < r; ++d)
                s -= Apk[rr + d] * x[d];
            x[r] = s * invd[r];
            invL[r * 17 + lane] = x[r];
        }
    }
}

// half-row panel solve: thread handles 8 of 16 cols of row i
__device__ __forceinline__ void panel_solve_half(float* __restrict__ Apk,
                                                 const float* __restrict__ invL,
                                                 int i, int k0, int half)
{
    const int ro = aoff(i) + k0;
    float r[16];
    #pragma unroll
    for (int c4 = 0; c4 < 4; ++c4) {
        float4 v = *reinterpret_cast<const float4*>(&Apk[ro + c4 * 4]);
        r[c4 * 4 + 0] = v.x; r[c4 * 4 + 1] = v.y;
        r[c4 * 4 + 2] = v.z; r[c4 * 4 + 3] = v.w;
    }
    const int cb = half * 8;
    #pragma unroll
    for (int cc = 0; cc < 8; ++cc) {
        const int c = cb + cc;
        float s = 0.0f;
        #pragma unroll
        for (int d = 0; d < 16; ++d)
            if (d <= c) s = fmaf(invL[c * 17 + d], r[d], s);
        Apk[ro + c] = s;
    }
}

__global__ __launch_bounds__(256, 4)
void chol_kernel(float* __restrict__ out)
{
    const int N = blockIdx.x;
    const int tid = threadIdx.x;
    const int wrp = tid >> 5;
    const int lane = tid & 31;
    float* c_out = out + (size_t)N_LOC * 16384 + (size_t)N * 16384;

    __shared__ float Apk[8448];        // packed lower triangle
    __shared__ float invd[16];
    __shared__ float invL[16 * 17];

    // ---- load packed triangle from scratch (coalesced float4) ----
    {
        const float4* src = reinterpret_cast<const float4*>(c_out);
        float4* dst = reinterpret_cast<float4*>(Apk);
        for (int idx = tid; idx < 2112; idx += 256)
            dst[idx] = src[idx];
    }
    __syncthreads();

    // ---- kb = 0: factor diag block 0 ----
    if (wrp == 0) diag_factor(Apk, invd, invL, 0, lane);
    __syncthreads();

    // ---- panel solve 0 (rows 16..127, 2 threads/row) ----
    if (tid < 224)
        panel_solve_half(Apk, invL, 16 + (tid >> 1), 0, tid & 1);
    __syncthreads();

    // ---- kb = 1..7: [warp0: diag update + factor || warps1-7: other tasks] ----
    #pragma unroll 1
    for (int kb = 1; kb < 8; ++kb) {
        const int k0 = kb * 16;
        const int kp = k0 - 16;
        const int rem = 112 - k0;
        const int B = 8 - kb;
        const int ntasks = B * (B + 1) / 2;

        if (wrp == 0) {
            warp_block_update(Apk, kb, kb, kp, lane, true);
            __syncwarp();
            diag_factor(Apk, invd, invL, k0, lane);
        } else {
            for (int t = wrp; t < ntasks; t += 7) {
                int bi, bj;
                tridec(t, bi, bj);
                warp_block_update(Apk, kb + bi, kb + bj, kp, lane, bi == bj);
            }
        }
        __syncthreads();

        if (rem > 0) {
            if (tid < 2 * rem)
                panel_solve_half(Apk, invL, k0 + 16 + (tid >> 1), k0, tid & 1);
            __syncthreads();
        }
    }
    __syncthreads();

    // ---- write chol: 2 threads/row (lower values, zeros above) ----
    {
        const int i = tid >> 1;
        const int ro = aoff(i);
        const int cbase = (tid & 1) * 64;
        float* crow = c_out + i * 128 + cbase;
        #pragma unroll 4
        for (int c4 = 0; c4 < 16; ++c4) {
            const int j0 = cbase + c4 * 4;
            float va[4];
            #pragma unroll
            for (int c = 0; c < 4; ++c)
                va[c] = (j0 + c <= i) ? Apk[ro + j0 + c] : 0.0f;
            *reinterpret_cast<float4*>(crow + c4 * 4) =
                make_float4(va[0], va[1], va[2], va[3]);
        }
    }
}

extern "C" void kernel_launch(void* const* d_in, const int* in_sizes, int n_in,
                              void* d_out, int out_size)
{
    const float* aug      = (const float*)d_in[0];
    const float* theta    = (const float*)d_in[1];
    const float* scales   = (const float*)d_in[2];
    const float* nug_mean = (const float*)d_in[3];
    const int*   bidx     = (const int*)d_in[4];
    float* out = (float*)d_out;

    gram_kernel<<<N_LOC, 512>>>(aug, theta, scales, nug_mean, bidx, out);
    chol_kernel<<<N_LOC, 256>>>(out);
}

// round 16
// speedup vs baseline: 1.0286x; 1.0286x over previous
#include <cuda_runtime.h>
#include <math.h>

#define N_LOC 4096
#define N_REP 128
#define M_NBR 48

// packed lower-triangle row offset (rows padded to multiples of 4)
__device__ __forceinline__ int aoff(int i) {
    int q = i >> 2;
    return 4 * (q + 1) * (2 * q + (i & 3));
}

__device__ __forceinline__ void tridec(int t, int& row, int& col) {
    int r = (int)((sqrtf(8.0f * (float)t + 1.0f) - 1.0f) * 0.5f);
    while ((r + 1) * (r + 2) / 2 <= t) ++r;
    while (r * (r + 1) / 2 > t) --r;
    row = r;
    col = t - r * (r + 1) / 2;
}

// ===================== Kernel 1: gram + Matern epilogue -> g =====================
__global__ __launch_bounds__(512, 3)
void gram_kernel(const float* __restrict__ aug,
                 const float* __restrict__ theta,
                 const float* __restrict__ scales,
                 const float* __restrict__ nug_mean,
                 const int* __restrict__ batch_idx,
                 float* __restrict__ out)
{
    const int N = blockIdx.x;
    const int tid = threadIdx.x;
    float* g_out = out + (size_t)N * 16384;

    if (batch_idx[N] == 0) {
        for (int idx = tid; idx < 16384; idx += 512)
            g_out[idx] = ((idx >> 7) == (idx & 127)) ? 1.0f : 0.0f;
        return;
    }

    __shared__ float xs[M_NBR * 128];
    __shared__ float diag[128];
    __shared__ float scalm[M_NBR];

    const float t2 = theta[2];
    const float t3 = theta[3];
    const float t4 = theta[4];
    const float t5 = theta[5];
    const float ls = expf(t5) * 1.7320508075688772f;
    const float inv_ls2 = 1.0f / (ls * ls);
    const float sig2 = expf(2.0f * (logf(scales[N]) * t4 + t3));
    const float inv_nug = 1.0f / nug_mean[N];

    if (tid < M_NBR)
        scalm[tid] = expf(-0.5f * (float)(tid + 1) * expf(t2));
    __syncthreads();

    {
        const float* base = aug + (size_t)N * (M_NBR + 1) + 1;
        for (int idx = tid; idx < N_REP * M_NBR; idx += 512) {
            int i = idx / M_NBR;
            int m = idx - i * M_NBR;
            float v = base[(size_t)i * ((size_t)N_LOC * (M_NBR + 1)) + m];
            if (v != v) v = 0.0f;
            xs[m * 128 + i] = v * scalm[m];
        }
    }
    __syncthreads();

    if (tid < N_REP) {
        float d = 0.0f;
        #pragma unroll
        for (int m = 0; m < M_NBR; ++m) {
            float v = xs[m * 128 + tid];
            d = fmaf(v, v, d);
        }
        diag[tid] = d;
    }
    __syncthreads();

    for (int t = tid; t < 528; t += 512) {
        int ti, tj;
        tridec(t, ti, tj);
        const int ib = ti * 4, jb = tj * 4;

        float acc[16];
        #pragma unroll
        for (int k = 0; k < 16; ++k) acc[k] = 0.0f;

        #pragma unroll 4
        for (int m = 0; m < M_NBR; ++m) {
            const float* row = xs + m * 128;
            float4 a = *reinterpret_cast<const float4*>(row + ib);
            float4 b = *reinterpret_cast<const float4*>(row + jb);
            float av[4] = {a.x, a.y, a.z, a.w};
            float bv[4] = {b.x, b.y, b.z, b.w};
            #pragma unroll
            for (int r = 0; r < 4; ++r)
                #pragma unroll
                for (int c = 0; c < 4; ++c)
                    acc[r * 4 + c] = fmaf(av[r], bv[c], acc[r * 4 + c]);
        }

        float di[4], dj[4];
        #pragma unroll
        for (int r = 0; r < 4; ++r) di[r] = diag[ib + r];
        #pragma unroll
        for (int c = 0; c < 4; ++c) dj[c] = diag[jb + c];

        #pragma unroll
        for (int r = 0; r < 4; ++r)
            #pragma unroll
            for (int c = 0; c < 4; ++c) {
                float G = acc[r * 4 + c];
                float sq = fmaxf((di[r] + dj[c] - 2.0f * G) * inv_ls2, 0.0f);
                float s3 = 1.7320508075688772f * sq * __frsqrt_rn(fmaxf(sq, 1e-30f));
                float mat = (1.0f + s3) * __expf(-s3);
                acc[r * 4 + c] = (G + sig2 * mat) * inv_nug
                               + ((ib + r == jb + c) ? 1.0f : 0.0f);
            }

        #pragma unroll
        for (int r = 0; r < 4; ++r)
            *reinterpret_cast<float4*>(g_out + (ib + r) * 128 + jb) =
                make_float4(acc[r * 4], acc[r * 4 + 1], acc[r * 4 + 2], acc[r * 4 + 3]);
        if (ti > tj) {
            #pragma unroll
            for (int c = 0; c < 4; ++c)
                *reinterpret_cast<float4*>(g_out + (jb + c) * 128 + ib) =
                    make_float4(acc[c], acc[4 + c], acc[8 + c], acc[12 + c]);
        }
    }
}

// ===================== Kernel 2: batched Cholesky ===============================

// Single-block warp update (16x16), as in R14.
__device__ __forceinline__ void warp_block_update(float* __restrict__ Apk,
                                                  int I, int J, int kp,
                                                  int lane, bool isdiag)
{
    const int lr = lane >> 3;
    const int lc = lane & 7;
    const int lrow = lane >> 1;
    const int h8 = (lane & 1) << 3;

    float areg[8], breg[8];
    {
        const float* p = &Apk[aoff((I << 4) + lrow) + kp + h8];
        float4 v0 = *reinterpret_cast<const float4*>(p);
        float4 v1 = *reinterpret_cast<const float4*>(p + 4);
        areg[0] = v0.x; areg[1] = v0.y; areg[2] = v0.z; areg[3] = v0.w;
        areg[4] = v1.x; areg[5] = v1.y; areg[6] = v1.z; areg[7] = v1.w;
    }
    if (isdiag) {
        #pragma unroll
        for (int q = 0; q < 8; ++q) breg[q] = areg[q];
    } else {
        const float* p = &Apk[aoff((J << 4) + lrow) + kp + h8];
        float4 v0 = *reinterpret_cast<const float4*>(p);
        float4 v1 = *reinterpret_cast<const float4*>(p + 4);
        breg[0] = v0.x; breg[1] = v0.y; breg[2] = v0.z; breg[3] = v0.w;
        breg[4] = v1.x; breg[5] = v1.y; breg[6] = v1.z; breg[7] = v1.w;
    }

    float acc[8];
    #pragma unroll
    for (int k = 0; k < 8; ++k) acc[k] = 0.0f;

    const int ra = lr << 2;
    const int ca = lc << 1;

    #pragma unroll
    for (int d = 0; d < 16; ++d) {
        const int dh = d >> 3;
        const int di = d & 7;
        float a0 = __shfl_sync(0xffffffffu, areg[di], ((ra + 0) << 1) | dh);
        float a1 = __shfl_sync(0xffffffffu, areg[di], ((ra + 1) << 1) | dh);
        float a2 = __shfl_sync(0xffffffffu, areg[di], ((ra + 2) << 1) | dh);
        float a3 = __shfl_sync(0xffffffffu, areg[di], ((ra + 3) << 1) | dh);
        float b0 = __shfl_sync(0xffffffffu, breg[di], ((ca + 0) << 1) | dh);
        float b1 = __shfl_sync(0xffffffffu, breg[di], ((ca + 1) << 1) | dh);
        acc[0] = fmaf(a0, b0, acc[0]); acc[1] = fmaf(a0, b1, acc[1]);
        acc[2] = fmaf(a1, b0, acc[2]); acc[3] = fmaf(a1, b1, acc[3]);
        acc[4] = fmaf(a2, b0, acc[4]); acc[5] = fmaf(a2, b1, acc[5]);
        acc[6] = fmaf(a3, b0, acc[6]); acc[7] = fmaf(a3, b1, acc[7]);
    }

    const int ob = (J << 4) + ca;
    #pragma unroll
    for (int r = 0; r < 4; ++r) {
        const int il = ra + r;
        float* p = &Apk[aoff((I << 4) + il) + ob];
        if (!isdiag) {
            float2 v = *reinterpret_cast<float2*>(p);
            v.x -= acc[r * 2 + 0];
            v.y -= acc[r * 2 + 1];
            *reinterpret_cast<float2*>(p) = v;
        } else {
            if (ca     <= il) p[0] -= acc[r * 2 + 0];
            if (ca + 1 <= il) p[1] -= acc[r * 2 + 1];
        }
    }
}

// Paired update: out = 16 rows (block I) x 32 cols (blocks J, J+1), both off-diag.
// Half-warp cb = lane>>4 owns B block J+cb: lane 16*cb+l4 holds B-row l4 (16 cols)
// in breg[0..15] (compile-time indexed). A shuffles shared across halves.
// Per k-step: 8 shfl : 16 FMA.
__device__ __forceinline__ void warp_pair_update(float* __restrict__ Apk,
                                                 int I, int J, int kp, int lane)
{
    const int lrow = lane >> 1;
    const int h8 = (lane & 1) << 3;
    const int cb = lane >> 4;          // which B block this half-warp holds
    const int l4 = lane & 15;

    float areg[8];
    {
        const float* p = &Apk[aoff((I << 4) + lrow) + kp + h8];
        float4 v0 = *reinterpret_cast<const float4*>(p);
        float4 v1 = *reinterpret_cast<const float4*>(p + 4);
        areg[0] = v0.x; areg[1] = v0.y; areg[2] = v0.z; areg[3] = v0.w;
        areg[4] = v1.x; areg[5] = v1.y; areg[6] = v1.z; areg[7] = v1.w;
    }
    float breg[16];
    {
        const float* p = &Apk[aoff(((J + cb) << 4) + l4) + kp];
        #pragma unroll
        for (int q = 0; q < 4; ++q) {
            float4 v = *reinterpret_cast<const float4*>(p + q * 4);
            breg[q * 4 + 0] = v.x; breg[q * 4 + 1] = v.y;
            breg[q * 4 + 2] = v.z; breg[q * 4 + 3] = v.w;
        }
    }

    float acc[16];
    #pragma unroll
    for (int k = 0; k < 16; ++k) acc[k] = 0.0f;

    const int ra = (l4 >> 2) << 2;     // 0,4,8,12  (output rows, local)
    const int cl = (l4 & 3) << 2;      // 0,4,8,12  (output cols, local in block J+cb)
    const int bbase = lane & 16;       // holder half base

    #pragma unroll
    for (int d = 0; d < 16; ++d) {
        const int dh = d >> 3;
        const int di = d & 7;
        float a0 = __shfl_sync(0xffffffffu, areg[di], ((ra + 0) << 1) | dh);
        float a1 = __shfl_sync(0xffffffffu, areg[di], ((ra + 1) << 1) | dh);
        float a2 = __shfl_sync(0xffffffffu, areg[di], ((ra + 2) << 1) | dh);
        float a3 = __shfl_sync(0xffffffffu, areg[di], ((ra + 3) << 1) | dh);
        float b0 = __shfl_sync(0xffffffffu, breg[d], bbase + cl + 0);
        float b1 = __shfl_sync(0xffffffffu, breg[d], bbase + cl + 1);
        float b2 = __shfl_sync(0xffffffffu, breg[d], bbase + cl + 2);
        float b3 = __shfl_sync(0xffffffffu, breg[d], bbase + cl + 3);
        acc[0]  = fmaf(a0, b0, acc[0]);  acc[1]  = fmaf(a0, b1, acc[1]);
        acc[2]  = fmaf(a0, b2, acc[2]);  acc[3]  = fmaf(a0, b3, acc[3]);
        acc[4]  = fmaf(a1, b0, acc[4]);  acc[5]  = fmaf(a1, b1, acc[5]);
        acc[6]  = fmaf(a1, b2, acc[6]);  acc[7]  = fmaf(a1, b3, acc[7]);
        acc[8]  = fmaf(a2, b0, acc[8]);  acc[9]  = fmaf(a2, b1, acc[9]);
        acc[10] = fmaf(a2, b2, acc[10]); acc[11] = fmaf(a2, b3, acc[11]);
        acc[12] = fmaf(a3, b0, acc[12]); acc[13] = fmaf(a3, b1, acc[13]);
        acc[14] = fmaf(a3, b2, acc[14]); acc[15] = fmaf(a3, b3, acc[15]);
    }

    const int ob = ((J + cb) << 4) + cl;
    #pragma unroll
    for (int r = 0; r < 4; ++r) {
        float* p = &Apk[aoff((I << 4) + ra + r) + ob];
        float4 v = *reinterpret_cast<float4*>(p);
        v.x -= acc[r * 4 + 0];
        v.y -= acc[r * 4 + 1];
        v.z -= acc[r * 4 + 2];
        v.w -= acc[r * 4 + 3];
        *reinterpret_cast<float4*>(p) = v;
    }
}

// warp0: factor 16x16 diag block at k0 (in Apk), produce invd + invL.
__device__ __forceinline__ void diag_factor(float* __restrict__ Apk,
                                            float* __restrict__ invd,
                                            float* __restrict__ invL,
                                            int k0, int lane)
{
    float rw[16];
    const int ro = (lane < 16) ? (aoff(k0 + lane) + k0) : 0;
    if (lane < 16) {
        #pragma unroll
        for (int j = 0; j < 16; ++j)
            rw[j] = (j <= lane) ? Apk[ro + j] : 0.0f;
    } else {
        #pragma unroll
        for (int j = 0; j < 16; ++j) rw[j] = 0.0f;
    }
    #pragma unroll
    for (int c = 0; c < 16; ++c) {
        float dcc = __shfl_sync(0xffffffffu, rw[c], c);
        float lcc = sqrtf(dcc);
        float inv = 1.0f / lcc;
        if (lane == c) { rw[c] = lcc; invd[c] = inv; }
        else if (lane > c && lane < 16) rw[c] *= inv;
        float vc = rw[c];
        #pragma unroll
        for (int j = c + 1; j < 16; ++j) {
            float vj = __shfl_sync(0xffffffffu, vc, j);
            if (lane >= j && lane < 16) rw[j] -= vc * vj;
        }
    }
    if (lane < 16) {
        #pragma unroll
        for (int j = 0; j < 16; ++j)
            if (j <= lane) Apk[ro + j] = rw[j];
    }
    __syncwarp();
    // inv(L11) column `lane`
    if (lane < 16) {
        float x[16];
        #pragma unroll
        for (int r = 0; r < 16; ++r) {
            float s = (r == lane) ? 1.0f : 0.0f;
            const int rr = aoff(k0 + r) + k0;
            #pragma unroll
            for (int d = 0; d < r; ++d)
                s -= Apk[rr + d] * x[d];
            x[r] = s * invd[r];
            invL[r * 17 + lane] = x[r];
        }
    }
}

__global__ __launch_bounds__(128, 6)
void chol_kernel(float* __restrict__ out)
{
    const int N = blockIdx.x;
    const int tid = threadIdx.x;
    const int wrp = tid >> 5;
    const int lane = tid & 31;
    const float* g_in = out + (size_t)N * 16384;
    float* c_out = out + (size_t)N_LOC * 16384 + (size_t)N * 16384;

    __shared__ float Apk[8448];
    __shared__ float invd[16];
    __shared__ float invL[16 * 17];

    // ---- load lower triangle of g into packed smem; thread = row ----
    {
        const int i = tid;
        const int ro = aoff(i);
        const int nch = (i >> 2) + 1;
        const float* grow = g_in + i * 128;
        for (int c4 = 0; c4 < nch; ++c4)
            *reinterpret_cast<float4*>(&Apk[ro + c4 * 4]) =
                *reinterpret_cast<const float4*>(grow + c4 * 4);
    }
    __syncthreads();

    // ---- kb = 0: factor diag block 0 ----
    if (wrp == 0) diag_factor(Apk, invd, invL, 0, lane);
    __syncthreads();

    // ---- panel solve 0 (rows 16..127) ----
    if (tid < 112) {
        const int i = 16 + tid;
        const int ro = aoff(i);
        float r[16];
        #pragma unroll
        for (int c4 = 0; c4 < 4; ++c4) {
            float4 v = *reinterpret_cast<const float4*>(&Apk[ro + c4 * 4]);
            r[c4 * 4 + 0] = v.x; r[c4 * 4 + 1] = v.y;
            r[c4 * 4 + 2] = v.z; r[c4 * 4 + 3] = v.w;
        }
        #pragma unroll
        for (int c = 0; c < 16; ++c) {
            float s = 0.0f;
            #pragma unroll
            for (int d = 0; d <= c; ++d)
                s = fmaf(invL[c * 17 + d], r[d], s);
            Apk[ro + c] = s;
        }
    }
    __syncthreads();

    // ---- kb = 1..7: [warp0: diag update + factor || warps1-3: paired tasks] ----
    #pragma unroll 1
    for (int kb = 1; kb < 8; ++kb) {
        const int k0 = kb * 16;
        const int kp = k0 - 16;
        const int rem = 112 - k0;

        if (wrp == 0) {
            warp_block_update(Apk, kb, kb, kp, lane, true);
            __syncwarp();
            diag_factor(Apk, invd, invL, k0, lane);
        } else {
            int cnt = 0;
            for (int I = kb + 1; I <= 7; ++I) {
                const int m = I - kb;
                const int npair = m >> 1;
                const int odd = m & 1;
                const int nslot = npair + odd + 1;
                for (int s = 0; s < nslot; ++s, ++cnt) {
                    if (cnt % 3 != wrp - 1) continue;
                    if (s < npair)
                        warp_pair_update(Apk, I, kb + 2 * s, kp, lane);
                    else if (odd && s == npair)
                        warp_block_update(Apk, I, I - 1, kp, lane, false);
                    else
                        warp_block_update(Apk, I, I, kp, lane, true);
                }
            }
        }
        __syncthreads();

        // panel solve kb (rows k0+16..127)
        if (rem > 0) {
            if (tid < rem) {
                const int i = k0 + 16 + tid;
                const int ro = aoff(i) + k0;
                float r[16];
                #pragma unroll
                for (int c4 = 0; c4 < 4; ++c4) {
                    float4 v = *reinterpret_cast<const float4*>(&Apk[ro + c4 * 4]);
                    r[c4 * 4 + 0] = v.x; r[c4 * 4 + 1] = v.y;
                    r[c4 * 4 + 2] = v.z; r[c4 * 4 + 3] = v.w;
                }
                #pragma unroll
                for (int c = 0; c < 16; ++c) {
                    float s = 0.0f;
                    #pragma unroll
                    for (int d = 0; d <= c; ++d)
                        s = fmaf(invL[c * 17 + d], r[d], s);
                    Apk[ro + c] = s;
                }
            }
            __syncthreads();
        }
    }
    __syncthreads();

    // ---- write chol: full row per thread (lower values, zeros above) ----
    {
        const int i = tid;
        const int ro = aoff(i);
        float* crow = c_out + i * 128;
        for (int c4 = 0; c4 < 32; ++c4) {
            const int j0 = c4 * 4;
            float va[4];
            #pragma unroll
            for (int c = 0; c < 4; ++c)
                va[c] = (j0 + c <= i) ? Apk[ro + j0 + c] : 0.0f;
            *reinterpret_cast<float4*>(crow + j0) =
                make_float4(va[0], va[1], va[2], va[3]);
        }
    }
}

extern "C" void kernel_launch(void* const* d_in, const int* in_sizes, int n_in,
                              void* d_out, int out_size)
{
    const float* aug      = (const float*)d_in[0];
    const float* theta    = (const float*)d_in[1];
    const float* scales   = (const float*)d_in[2];
    const float* nug_mean = (const float*)d_in[3];
    const int*   bidx     = (const int*)d_in[4];
    float* out = (float*)d_out;

    gram_kernel<<<N_LOC, 512>>>(aug, theta, scales, nug_mean, bidx, out);
    chol_kernel<<<N_LOC, 128>>>(out);
}

// round 17
// speedup vs baseline: 1.1783x; 1.1455x over previous
#include <cuda_runtime.h>
#include <math.h>

#define N_LOC 4096
#define N_REP 128
#define M_NBR 48

// packed lower-triangle row offset (rows padded to multiples of 4)
__device__ __forceinline__ int aoff(int i) {
    int q = i >> 2;
    return 4 * (q + 1) * (2 * q + (i & 3));
}

__device__ __forceinline__ void tridec(int t, int& row, int& col) {
    int r = (int)((sqrtf(8.0f * (float)t + 1.0f) - 1.0f) * 0.5f);
    while ((r + 1) * (r + 2) / 2 <= t) ++r;
    while (r * (r + 1) / 2 > t) --r;
    row = r;
    col = t - r * (r + 1) / 2;
}

// ===================== Kernel 1: gram + Matern epilogue -> g =====================
__global__ __launch_bounds__(512, 3)
void gram_kernel(const float* __restrict__ aug,
                 const float* __restrict__ theta,
                 const float* __restrict__ scales,
                 const float* __restrict__ nug_mean,
                 const int* __restrict__ batch_idx,
                 float* __restrict__ out)
{
    const int N = blockIdx.x;
    const int tid = threadIdx.x;
    float* g_out = out + (size_t)N * 16384;

    if (batch_idx[N] == 0) {
        for (int idx = tid; idx < 16384; idx += 512)
            g_out[idx] = ((idx >> 7) == (idx & 127)) ? 1.0f : 0.0f;
        return;
    }

    __shared__ float xs[M_NBR * 128];
    __shared__ float diag[128];
    __shared__ float scalm[M_NBR];

    const float t2 = theta[2];
    const float t3 = theta[3];
    const float t4 = theta[4];
    const float t5 = theta[5];
    const float ls = expf(t5) * 1.7320508075688772f;
    const float inv_ls2 = 1.0f / (ls * ls);
    const float sig2 = expf(2.0f * (logf(scales[N]) * t4 + t3));
    const float inv_nug = 1.0f / nug_mean[N];

    if (tid < M_NBR)
        scalm[tid] = expf(-0.5f * (float)(tid + 1) * expf(t2));
    __syncthreads();

    {
        const float* base = aug + (size_t)N * (M_NBR + 1) + 1;
        for (int idx = tid; idx < N_REP * M_NBR; idx += 512) {
            int i = idx / M_NBR;
            int m = idx - i * M_NBR;
            float v = base[(size_t)i * ((size_t)N_LOC * (M_NBR + 1)) + m];
            if (v != v) v = 0.0f;
            xs[m * 128 + i] = v * scalm[m];
        }
    }
    __syncthreads();

    if (tid < N_REP) {
        float d = 0.0f;
        #pragma unroll
        for (int m = 0; m < M_NBR; ++m) {
            float v = xs[m * 128 + tid];
            d = fmaf(v, v, d);
        }
        diag[tid] = d;
    }
    __syncthreads();

    for (int t = tid; t < 528; t += 512) {
        int ti, tj;
        tridec(t, ti, tj);
        const int ib = ti * 4, jb = tj * 4;

        float acc[16];
        #pragma unroll
        for (int k = 0; k < 16; ++k) acc[k] = 0.0f;

        #pragma unroll 4
        for (int m = 0; m < M_NBR; ++m) {
            const float* row = xs + m * 128;
            float4 a = *reinterpret_cast<const float4*>(row + ib);
            float4 b = *reinterpret_cast<const float4*>(row + jb);
            float av[4] = {a.x, a.y, a.z, a.w};
            float bv[4] = {b.x, b.y, b.z, b.w};
            #pragma unroll
            for (int r = 0; r < 4; ++r)
                #pragma unroll
                for (int c = 0; c < 4; ++c)
                    acc[r * 4 + c] = fmaf(av[r], bv[c], acc[r * 4 + c]);
        }

        float di[4], dj[4];
        #pragma unroll
        for (int r = 0; r < 4; ++r) di[r] = diag[ib + r];
        #pragma unroll
        for (int c = 0; c < 4; ++c) dj[c] = diag[jb + c];

        #pragma unroll
        for (int r = 0; r < 4; ++r)
            #pragma unroll
            for (int c = 0; c < 4; ++c) {
                float G = acc[r * 4 + c];
                float sq = fmaxf((di[r] + dj[c] - 2.0f * G) * inv_ls2, 0.0f);
                float s3 = 1.7320508075688772f * sq * __frsqrt_rn(fmaxf(sq, 1e-30f));
                float mat = (1.0f + s3) * __expf(-s3);
                acc[r * 4 + c] = (G + sig2 * mat) * inv_nug
                               + ((ib + r == jb + c) ? 1.0f : 0.0f);
            }

        #pragma unroll
        for (int r = 0; r < 4; ++r)
            *reinterpret_cast<float4*>(g_out + (ib + r) * 128 + jb) =
                make_float4(acc[r * 4], acc[r * 4 + 1], acc[r * 4 + 2], acc[r * 4 + 3]);
        if (ti > tj) {
            #pragma unroll
            for (int c = 0; c < 4; ++c)
                *reinterpret_cast<float4*>(g_out + (jb + c) * 128 + ib) =
                    make_float4(acc[c], acc[4 + c], acc[8 + c], acc[12 + c]);
        }
    }
}

// ===================== Kernel 2: batched Cholesky ===============================

// Warp-cooperative rank-16 update of 16x16 block (I,J), panel cols [kp,kp+16).
// Lane owns 4 rows x 2 cols: ra = (lane>>3)*4, ca = (lane&7)*2.
// Both operands read from smem with broadcast-friendly addressing (<=8 distinct
// addresses per LDS.128 instruction). No shuffles.
__device__ __forceinline__ void warp_block_update(float* __restrict__ Apk,
                                                  int I, int J, int kp,
                                                  int lane, bool isdiag)
{
    const int ra = (lane >> 3) << 2;
    const int ca = (lane & 7) << 1;

    int roi[4], roj[2];
    #pragma unroll
    for (int r = 0; r < 4; ++r) roi[r] = aoff((I << 4) + ra + r) + kp;
    #pragma unroll
    for (int c = 0; c < 2; ++c) roj[c] = aoff((J << 4) + ca + c) + kp;

    float acc[8];
    #pragma unroll
    for (int k = 0; k < 8; ++k) acc[k] = 0.0f;

    #pragma unroll
    for (int q = 0; q < 4; ++q) {
        float4 a4[4], b4[2];
        #pragma unroll
        for (int r = 0; r < 4; ++r)
            a4[r] = *reinterpret_cast<const float4*>(&Apk[roi[r] + q * 4]);
        #pragma unroll
        for (int c = 0; c < 2; ++c)
            b4[c] = *reinterpret_cast<const float4*>(&Apk[roj[c] + q * 4]);

        #pragma unroll
        for (int r = 0; r < 4; ++r)
            #pragma unroll
            for (int c = 0; c < 2; ++c) {
                float a = acc[r * 2 + c];
                a = fmaf(a4[r].x, b4[c].x, a);
                a = fmaf(a4[r].y, b4[c].y, a);
                a = fmaf(a4[r].z, b4[c].z, a);
                a = fmaf(a4[r].w, b4[c].w, a);
                acc[r * 2 + c] = a;
            }
    }

    const int ob = (J << 4) + ca;
    #pragma unroll
    for (int r = 0; r < 4; ++r) {
        const int il = ra + r;
        float* p = &Apk[aoff((I << 4) + il) + ob];
        if (!isdiag) {
            float2 v = *reinterpret_cast<float2*>(p);
            v.x -= acc[r * 2 + 0];
            v.y -= acc[r * 2 + 1];
            *reinterpret_cast<float2*>(p) = v;
        } else {
            if (ca     <= il) p[0] -= acc[r * 2 + 0];
            if (ca + 1 <= il) p[1] -= acc[r * 2 + 1];
        }
    }
}

// warp0: factor 16x16 diag block at k0 (in Apk), produce invd + invL.
__device__ __forceinline__ void diag_factor(float* __restrict__ Apk,
                                            float* __restrict__ invd,
                                            float* __restrict__ invL,
                                            int k0, int lane)
{
    float rw[16];
    const int ro = (lane < 16) ? (aoff(k0 + lane) + k0) : 0;
    if (lane < 16) {
        #pragma unroll
        for (int j = 0; j < 16; ++j)
            rw[j] = (j <= lane) ? Apk[ro + j] : 0.0f;
    } else {
        #pragma unroll
        for (int j = 0; j < 16; ++j) rw[j] = 0.0f;
    }
    #pragma unroll
    for (int c = 0; c < 16; ++c) {
        float dcc = __shfl_sync(0xffffffffu, rw[c], c);
        float lcc = sqrtf(dcc);
        float inv = 1.0f / lcc;
        if (lane == c) { rw[c] = lcc; invd[c] = inv; }
        else if (lane > c && lane < 16) rw[c] *= inv;
        float vc = rw[c];
        #pragma unroll
        for (int j = c + 1; j < 16; ++j) {
            float vj = __shfl_sync(0xffffffffu, vc, j);
            if (lane >= j && lane < 16) rw[j] -= vc * vj;
        }
    }
    if (lane < 16) {
        #pragma unroll
        for (int j = 0; j < 16; ++j)
            if (j <= lane) Apk[ro + j] = rw[j];
    }
    __syncwarp();
    // inv(L11) column `lane`
    if (lane < 16) {
        float x[16];
        #pragma unroll
        for (int r = 0; r < 16; ++r) {
            float s = (r == lane) ? 1.0f : 0.0f;
            const int rr = aoff(k0 + r) + k0;
            #pragma unroll
            for (int d = 0; d < r; ++d)
                s -= Apk[rr + d] * x[d];
            x[r] = s * invd[r];
            invL[r * 17 + lane] = x[r];
        }
    }
}

__global__ __launch_bounds__(128, 6)
void chol_kernel(float* __restrict__ out)
{
    const int N = blockIdx.x;
    const int tid = threadIdx.x;
    const int wrp = tid >> 5;
    const int lane = tid & 31;
    const float* g_in = out + (size_t)N * 16384;
    float* c_out = out + (size_t)N_LOC * 16384 + (size_t)N * 16384;

    __shared__ float Apk[8448];
    __shared__ float invd[16];
    __shared__ float invL[16 * 17];

    // ---- load lower triangle of g into packed smem; thread = row ----
    {
        const int i = tid;
        const int ro = aoff(i);
        const int nch = (i >> 2) + 1;
        const float* grow = g_in + i * 128;
        for (int c4 = 0; c4 < nch; ++c4)
            *reinterpret_cast<float4*>(&Apk[ro + c4 * 4]) =
                *reinterpret_cast<const float4*>(grow + c4 * 4);
    }
    __syncthreads();

    // ---- kb = 0: factor diag block 0 ----
    if (wrp == 0) diag_factor(Apk, invd, invL, 0, lane);
    __syncthreads();

    // ---- panel solve 0 (rows 16..127) ----
    if (tid < 112) {
        const int i = 16 + tid;
        const int ro = aoff(i);
        float r[16];
        #pragma unroll
        for (int c4 = 0; c4 < 4; ++c4) {
            float4 v = *reinterpret_cast<const float4*>(&Apk[ro + c4 * 4]);
            r[c4 * 4 + 0] = v.x; r[c4 * 4 + 1] = v.y;
            r[c4 * 4 + 2] = v.z; r[c4 * 4 + 3] = v.w;
        }
        #pragma unroll
        for (int c = 0; c < 16; ++c) {
            float s = 0.0f;
            #pragma unroll
            for (int d = 0; d <= c; ++d)
                s = fmaf(invL[c * 17 + d], r[d], s);
            Apk[ro + c] = s;
        }
    }
    __syncthreads();

    // ---- kb = 1..7: [warp0: diag update + factor || warps1-3: other tasks] ----
    #pragma unroll 1
    for (int kb = 1; kb < 8; ++kb) {
        const int k0 = kb * 16;
        const int kp = k0 - 16;
        const int rem = 112 - k0;
        const int B = 8 - kb;
        const int ntasks = B * (B + 1) / 2;

        if (wrp == 0) {
            warp_block_update(Apk, kb, kb, kp, lane, true);
            __syncwarp();
            diag_factor(Apk, invd, invL, k0, lane);
        } else {
            for (int t = wrp; t < ntasks; t += 3) {
                int bi, bj;
                tridec(t, bi, bj);
                warp_block_update(Apk, kb + bi, kb + bj, kp, lane, bi == bj);
            }
        }
        __syncthreads();

        // panel solve kb (rows k0+16..127)
        if (rem > 0) {
            if (tid < rem) {
                const int i = k0 + 16 + tid;
                const int ro = aoff(i) + k0;
                float r[16];
                #pragma unroll
                for (int c4 = 0; c4 < 4; ++c4) {
                    float4 v = *reinterpret_cast<const float4*>(&Apk[ro + c4 * 4]);
                    r[c4 * 4 + 0] = v.x; r[c4 * 4 + 1] = v.y;
                    r[c4 * 4 + 2] = v.z; r[c4 * 4 + 3] = v.w;
                }
                #pragma unroll
                for (int c = 0; c < 16; ++c) {
                    float s = 0.0f;
                    #pragma unroll
                    for (int d = 0; d <= c; ++d)
                        s = fmaf(invL[c * 17 + d], r[d], s);
                    Apk[ro + c] = s;
                }
            }
            __syncthreads();
        }
    }
    __syncthreads();

    // ---- write chol: full row per thread (lower values, zeros above) ----
    {
        const int i = tid;
        const int ro = aoff(i);
        float* crow = c_out + i * 128;
        for (int c4 = 0; c4 < 32; ++c4) {
            const int j0 = c4 * 4;
            float va[4];
            #pragma unroll
            for (int c = 0; c < 4; ++c)
                va[c] = (j0 + c <= i) ? Apk[ro + j0 + c] : 0.0f;
            *reinterpret_cast<float4*>(crow + j0) =
                make_float4(va[0], va[1], va[2], va[3]);
        }
    }
}

extern "C" void kernel_launch(void* const* d_in, const int* in_sizes, int n_in,
                              void* d_out, int out_size)
{
    const float* aug      = (const float*)d_in[0];
    const float* theta    = (const float*)d_in[1];
    const float* scales   = (const float*)d_in[2];
    const float* nug_mean = (const float*)d_in[3];
    const int*   bidx     = (const int*)d_in[4];
    float* out = (float*)d_out;

    gram_kernel<<<N_LOC, 512>>>(aug, theta, scales, nug_mean, bidx, out);
    chol_kernel<<<N_LOC, 128>>>(out);
}